// round 15
// baseline (speedup 1.0000x reference)
#include <cuda_runtime.h>
#include <math.h>

#define BATCH  128
#define KK     512
#define NSL    8      // i-slices of 64 rows
#define SLR    64
#define TPB    128    // thread owns 4 columns (float4)

#define LOGK 6.2383246250395077632f   // log(512)

// Scratch (__device__ globals). Fits in L2; streaming input loads use __ldcs
// (evict-first) so these stay resident.
__device__ float g_Ep0[NSL * BATCH * KK];   // partial col-sums of exp(Q0) (2 MB)
__device__ float g_Ep1[NSL * BATCH * KK];   // partial col-sums of exp(Q1) (2 MB)
__device__ float g_sp[BATCH * NSL];         // per-(b,slice) scalar partials of s[b]
__device__ float g_sb[BATCH];               // per-batch logK - log(s[b])
__device__ unsigned int g_bt[BATCH];        // K2 blocks done per batch (to 8)
__device__ unsigned int g_tickF;            // batches finished (to 128)
// Counters zero-initialized; reset by their last user each launch.

__device__ __forceinline__ float4 ldcs4(const float4* p) { return __ldcs(p); }

// ---------------------------------------------------------------------------
// Kernel 1 (fence-free streaming, measured 42.4us / 81% DRAM in R10):
// partial column sums of exp() for Q0 and Q1.
// grid = (2*NSL, BATCH) = 2048 blocks = one full wave at 14 blocks/SM.
// ---------------------------------------------------------------------------
__global__ void __launch_bounds__(TPB, 14) k_colsum(const float* __restrict__ Q0,
                                                    const float* __restrict__ Q1)
{
    const int which = blockIdx.x >> 3;
    const int slice = blockIdx.x & 7;
    const int b     = blockIdx.y;
    const int t     = threadIdx.x;

    const float* __restrict__ src = which ? Q1 : Q0;
    float* __restrict__ dst = which ? g_Ep1 : g_Ep0;

    const float4* p = (const float4*)(src + (size_t)b * KK * KK
                                          + (size_t)(slice * SLR) * KK) + t;
    const int rs = KK / 4;

    float sx = 0.f, sy = 0.f, sz = 0.f, sw = 0.f;
#pragma unroll
    for (int i = 0; i < SLR; i += 4) {
        float4 a0 = ldcs4(p + (i + 0) * rs);
        float4 a1 = ldcs4(p + (i + 1) * rs);
        float4 a2 = ldcs4(p + (i + 2) * rs);
        float4 a3 = ldcs4(p + (i + 3) * rs);
        sx += __expf(a0.x) + __expf(a1.x) + __expf(a2.x) + __expf(a3.x);
        sy += __expf(a0.y) + __expf(a1.y) + __expf(a2.y) + __expf(a3.y);
        sz += __expf(a0.z) + __expf(a1.z) + __expf(a2.z) + __expf(a3.z);
        sw += __expf(a0.w) + __expf(a1.w) + __expf(a2.w) + __expf(a3.w);
    }
    ((float4*)(dst + ((size_t)slice * BATCH + b) * KK))[t] =
        make_float4(sx, sy, sz, sw);
}

// ---------------------------------------------------------------------------
// Kernel 2: folded mid pass. Per block (slice,b):
//   prologue: ew[i] = exp(P0)*K/E1 (smem, 64 i's);
//             w4    = exp(P2[j])/E0[j] for this thread's 4 j's (registers).
//   main loop (identical shape to proven streaming body): sx..sw over P1.
//   acc = dot(s, w4) -> block-reduce -> g_sp[b*NSL+slice]  (ONE scalar/block).
//   Lightweight per-batch ticket: last of 8 blocks sums 8 scalars -> g_sb[b];
//   global ticket -> one block does the deterministic batch tree-sum -> out.
// Eliminates g_mmp (4 MB round trip) and the k_final launch entirely.
// grid = (NSL, BATCH) = 1024 blocks, block = 128.
// ---------------------------------------------------------------------------
__global__ void __launch_bounds__(TPB, 14) k_mid(const float* __restrict__ P0,
                                                 const float* __restrict__ P1,
                                                 const float* __restrict__ P2,
                                                 float* __restrict__ out)
{
    const int slice = blockIdx.x;
    const int b     = blockIdx.y;
    const int t     = threadIdx.x;
    const int i0    = slice * SLR;

    // ew prologue (L2-hot Ep1 partials + P0)
    __shared__ float ew[SLR];
    if (t < SLR) {
        const int i = i0 + t;
        float e1 = g_Ep1[((size_t)0 * BATCH + b) * KK + i];
#pragma unroll
        for (int s = 1; s < NSL; s++)
            e1 += g_Ep1[((size_t)s * BATCH + b) * KK + i];
        ew[t] = __expf(P0[b * KK + i]) * (float)KK / e1;
    }

    // per-thread j-weights: w4 = exp(P2[j]) / E0[j] for columns 4t..4t+3
    float4 e0 = ((const float4*)(g_Ep0 + ((size_t)0 * BATCH + b) * KK))[t];
#pragma unroll
    for (int s = 1; s < NSL; s++) {
        float4 c = ((const float4*)(g_Ep0 + ((size_t)s * BATCH + b) * KK))[t];
        e0.x += c.x; e0.y += c.y; e0.z += c.z; e0.w += c.w;
    }
    float4 p2 = ((const float4*)(P2 + (size_t)b * KK))[t];
    float4 w4 = make_float4(__expf(p2.x) / e0.x, __expf(p2.y) / e0.y,
                            __expf(p2.z) / e0.z, __expf(p2.w) / e0.w);
    __syncthreads();

    const float4* p = (const float4*)(P1 + (size_t)b * KK * KK
                                         + (size_t)i0 * KK) + t;
    const int rs = KK / 4;

    float sx = 0.f, sy = 0.f, sz = 0.f, sw = 0.f;
#pragma unroll
    for (int i = 0; i < SLR; i += 4) {
        float4 a0 = ldcs4(p + (i + 0) * rs);
        float4 a1 = ldcs4(p + (i + 1) * rs);
        float4 a2 = ldcs4(p + (i + 2) * rs);
        float4 a3 = ldcs4(p + (i + 3) * rs);
        float w0 = ew[i + 0], w1 = ew[i + 1], w2 = ew[i + 2], w3 = ew[i + 3];
        sx += w0 * __expf(a0.x) + w1 * __expf(a1.x)
            + w2 * __expf(a2.x) + w3 * __expf(a3.x);
        sy += w0 * __expf(a0.y) + w1 * __expf(a1.y)
            + w2 * __expf(a2.y) + w3 * __expf(a3.y);
        sz += w0 * __expf(a0.z) + w1 * __expf(a1.z)
            + w2 * __expf(a2.z) + w3 * __expf(a3.z);
        sw += w0 * __expf(a0.w) + w1 * __expf(a1.w)
            + w2 * __expf(a2.w) + w3 * __expf(a3.w);
    }
    float acc = sx * w4.x + sy * w4.y + sz * w4.z + sw * w4.w;

    // block reduction to one scalar (fixed order -> deterministic)
#pragma unroll
    for (int o = 16; o; o >>= 1)
        acc += __shfl_down_sync(0xFFFFFFFFu, acc, o);
    __shared__ float red[4];
    if ((t & 31) == 0) red[t >> 5] = acc;
    __syncthreads();

    // ---- lightweight per-batch ticket (one scalar written per block) ----
    __shared__ bool amLast;
    if (t == 0) {
        g_sp[b * NSL + slice] = (red[0] + red[1]) + (red[2] + red[3]);
        __threadfence();          // release the scalar
        amLast = (atomicAdd(&g_bt[b], 1u) == NSL - 1);
    }
    __syncthreads();

    if (amLast) {
        __shared__ bool amFinal;
        if (t == 0) {
            __threadfence();      // acquire all 8 scalars of batch b
            float s = ((g_sp[b * NSL + 0] + g_sp[b * NSL + 1])
                     + (g_sp[b * NSL + 2] + g_sp[b * NSL + 3]))
                    + ((g_sp[b * NSL + 4] + g_sp[b * NSL + 5])
                     + (g_sp[b * NSL + 6] + g_sp[b * NSL + 7]));
            g_sb[b] = LOGK - logf(s);
            g_bt[b] = 0;          // reset per-batch ticket for replay
            __threadfence();
            amFinal = (atomicAdd(&g_tickF, 1u) == BATCH - 1);
        }
        __syncthreads();

        if (amFinal) {
            // one block: fixed-order tree sum over batches -> deterministic
            __shared__ float sm[BATCH];
            sm[t] = g_sb[t];
            __syncthreads();
#pragma unroll
            for (int off = BATCH / 2; off > 0; off >>= 1) {
                if (t < off) sm[t] += sm[t + off];
                __syncthreads();
            }
            if (t == 0) {
                out[0] = sm[0];
                g_tickF = 0;      // reset for graph replay
            }
        }
    }
}

// ---------------------------------------------------------------------------
extern "C" void kernel_launch(void* const* d_in, const int* in_sizes, int n_in,
                              void* d_out, int out_size)
{
    const float* Q0 = (const float*)d_in[0];  // logQ0 [B,K,K]
    const float* Q1 = (const float*)d_in[1];  // logQ1 [B,K,K]
    const float* P0 = (const float*)d_in[2];  // logP0 [B,1,K]
    const float* P1 = (const float*)d_in[3];  // logP1 [B,K,K]
    const float* P2 = (const float*)d_in[4];  // logP2 [B,K,1]

    dim3 g1(2 * NSL, BATCH);
    k_colsum<<<g1, TPB>>>(Q0, Q1);

    dim3 g2(NSL, BATCH);
    k_mid<<<g2, TPB>>>(P0, P1, P2, (float*)d_out);
}

// round 16
// speedup vs baseline: 1.0425x; 1.0425x over previous
#include <cuda_runtime.h>
#include <math.h>

#define BATCH  128
#define KK     512
#define NSL    8      // i-slices of 64 rows (K2 paths)
#define SLR    64
#define NSL1   16     // E1 partial rows (K1 writes 2 per block)
#define TPB    128
#define JSPL   4      // j-chunks in k_final

#define LOGK 6.2383246250395077632f   // log(512)

// Scratch (__device__ globals). Fits in L2; streaming input loads use __ldcs
// (evict-first) so these stay resident.
__device__ float g_Ep0[NSL  * BATCH * KK];  // partial col-sums of exp(Q0) (2 MB)
__device__ float g_Ep1[NSL1 * BATCH * KK];  // partial col-sums of exp(Q1) (4 MB)
__device__ float g_mmp[NSL  * BATCH * KK];  // partial mm sums (2 MB)
__device__ float g_sp[BATCH * JSPL];        // per-(b,chunk) t partial sums
__device__ unsigned int g_tickF;            // zero-init; last block resets

__device__ __forceinline__ float4 ldcs4(const float4* p) { return __ldcs(p); }

// ---------------------------------------------------------------------------
// Kernel 1: partial column sums of exp(Q1) (E1 partials for ew).
// grid = (NSL, BATCH) = 1024 blocks x 256 threads = 7 blocks/SM x 256 =
// 1792 threads/SM (FULL thread occupancy, unlike the 128-thread half-machine
// version). Threads split the 64-row slice: t<128 -> rows 0-31 (partial row
// 2*slice), t>=128 -> rows 32-63 (partial row 2*slice+1).
// ---------------------------------------------------------------------------
__global__ void __launch_bounds__(256, 7) k_colsum_q1(const float* __restrict__ Q1)
{
    const int slice = blockIdx.x;
    const int b     = blockIdx.y;
    const int t     = threadIdx.x;
    const int c     = t & 127;      // float4 column
    const int rh    = t >> 7;       // row half (0 or 1)

    const float4* p = (const float4*)(Q1 + (size_t)b * KK * KK
                                         + (size_t)(slice * SLR + rh * 32) * KK) + c;
    const int rs = KK / 4;

    float sx = 0.f, sy = 0.f, sz = 0.f, sw = 0.f;
#pragma unroll
    for (int i = 0; i < 32; i += 4) {
        float4 a0 = ldcs4(p + (i + 0) * rs);
        float4 a1 = ldcs4(p + (i + 1) * rs);
        float4 a2 = ldcs4(p + (i + 2) * rs);
        float4 a3 = ldcs4(p + (i + 3) * rs);
        sx += __expf(a0.x) + __expf(a1.x) + __expf(a2.x) + __expf(a3.x);
        sy += __expf(a0.y) + __expf(a1.y) + __expf(a2.y) + __expf(a3.y);
        sz += __expf(a0.z) + __expf(a1.z) + __expf(a2.z) + __expf(a3.z);
        sw += __expf(a0.w) + __expf(a1.w) + __expf(a2.w) + __expf(a3.w);
    }
    ((float4*)(g_Ep1 + ((size_t)(slice * 2 + rh) * BATCH + b) * KK))[c] =
        make_float4(sx, sy, sz, sw);
}

// ---------------------------------------------------------------------------
// Kernel 2 (heterogeneous, one wave): grid = (2*NSL, BATCH) = 2048 blocks.
//   blockIdx.x <  NSL : mid-path  — mmp[b,j] partial over P1 slice, using
//                       ew built inline from L2-hot g_Ep1 + P0.
//   blockIdx.x >= NSL : colsum-path over the matching Q0 slice.
// __launch_bounds__(128, 14) keeps regs <= 36 -> one full wave.
// ---------------------------------------------------------------------------
__global__ void __launch_bounds__(TPB, 14) k_mid_q0(const float* __restrict__ P0,
                                                    const float* __restrict__ P1,
                                                    const float* __restrict__ Q0)
{
    const int b = blockIdx.y;
    const int t = threadIdx.x;
    const int rs = KK / 4;

    if (blockIdx.x < NSL) {
        // ----- mid path: P1 slice -----
        const int slice = blockIdx.x;
        const int i0    = slice * SLR;

        __shared__ float ew[SLR];
        if (t < SLR) {
            const int i = i0 + t;
            float e1 = 0.f;
#pragma unroll
            for (int s = 0; s < NSL1; s++)
                e1 += g_Ep1[((size_t)s * BATCH + b) * KK + i];
            ew[t] = __expf(P0[b * KK + i]) * (float)KK / e1;
        }
        __syncthreads();

        const float4* p = (const float4*)(P1 + (size_t)b * KK * KK
                                             + (size_t)i0 * KK) + t;

        float sx = 0.f, sy = 0.f, sz = 0.f, sw = 0.f;
#pragma unroll
        for (int i = 0; i < SLR; i += 4) {
            float4 a0 = ldcs4(p + (i + 0) * rs);
            float4 a1 = ldcs4(p + (i + 1) * rs);
            float4 a2 = ldcs4(p + (i + 2) * rs);
            float4 a3 = ldcs4(p + (i + 3) * rs);
            float w0 = ew[i + 0], w1 = ew[i + 1], w2 = ew[i + 2], w3 = ew[i + 3];
            sx += w0 * __expf(a0.x) + w1 * __expf(a1.x)
                + w2 * __expf(a2.x) + w3 * __expf(a3.x);
            sy += w0 * __expf(a0.y) + w1 * __expf(a1.y)
                + w2 * __expf(a2.y) + w3 * __expf(a3.y);
            sz += w0 * __expf(a0.z) + w1 * __expf(a1.z)
                + w2 * __expf(a2.z) + w3 * __expf(a3.z);
            sw += w0 * __expf(a0.w) + w1 * __expf(a1.w)
                + w2 * __expf(a2.w) + w3 * __expf(a3.w);
        }
        ((float4*)(g_mmp + ((size_t)slice * BATCH + b) * KK))[t] =
            make_float4(sx, sy, sz, sw);
    } else {
        // ----- colsum path: Q0 slice -----
        const int slice = blockIdx.x - NSL;

        const float4* p = (const float4*)(Q0 + (size_t)b * KK * KK
                                             + (size_t)(slice * SLR) * KK) + t;

        float sx = 0.f, sy = 0.f, sz = 0.f, sw = 0.f;
#pragma unroll
        for (int i = 0; i < SLR; i += 4) {
            float4 a0 = ldcs4(p + (i + 0) * rs);
            float4 a1 = ldcs4(p + (i + 1) * rs);
            float4 a2 = ldcs4(p + (i + 2) * rs);
            float4 a3 = ldcs4(p + (i + 3) * rs);
            sx += __expf(a0.x) + __expf(a1.x) + __expf(a2.x) + __expf(a3.x);
            sy += __expf(a0.y) + __expf(a1.y) + __expf(a2.y) + __expf(a3.y);
            sz += __expf(a0.z) + __expf(a1.z) + __expf(a2.z) + __expf(a3.z);
            sw += __expf(a0.w) + __expf(a1.w) + __expf(a2.w) + __expf(a3.w);
        }
        ((float4*)(g_Ep0 + ((size_t)slice * BATCH + b) * KK))[t] =
            make_float4(sx, sy, sz, sw);
    }
}

// ---------------------------------------------------------------------------
// Kernel 3: t partials + deterministic finish.
// grid = (JSPL, BATCH) = 512 blocks, block = 128.
// ---------------------------------------------------------------------------
__global__ void __launch_bounds__(TPB) k_final(const float* __restrict__ P2,
                                               float* __restrict__ out)
{
    const int js = blockIdx.x;
    const int b  = blockIdx.y;
    const int t  = threadIdx.x;
    const int j  = js * TPB + t;

    float m = 0.f, e0 = 0.f;
#pragma unroll
    for (int s = 0; s < NSL; s++) {
        m  += g_mmp[((size_t)s * BATCH + b) * KK + j];
        e0 += g_Ep0[((size_t)s * BATCH + b) * KK + j];
    }
    float acc = m / e0 * __expf(P2[b * KK + j]);

#pragma unroll
    for (int o = 16; o; o >>= 1)
        acc += __shfl_down_sync(0xFFFFFFFFu, acc, o);

    __shared__ float red[4];
    if ((t & 31) == 0) red[t >> 5] = acc;
    __syncthreads();

    __shared__ bool amLast;
    if (t == 0) {
        g_sp[b * JSPL + js] = (red[0] + red[1]) + (red[2] + red[3]);
        __threadfence();
        amLast = (atomicAdd(&g_tickF, 1u) == BATCH * JSPL - 1);
    }
    __syncthreads();

    if (amLast) {
        __shared__ float sm[BATCH];
        float s = (g_sp[t * JSPL + 0] + g_sp[t * JSPL + 1])
                + (g_sp[t * JSPL + 2] + g_sp[t * JSPL + 3]);
        sm[t] = LOGK - logf(s);
        __syncthreads();
#pragma unroll
        for (int off = BATCH / 2; off > 0; off >>= 1) {
            if (t < off) sm[t] += sm[t + off];
            __syncthreads();
        }
        if (t == 0) {
            out[0] = sm[0];
            g_tickF = 0;   // reset for graph replay
        }
    }
}

// ---------------------------------------------------------------------------
extern "C" void kernel_launch(void* const* d_in, const int* in_sizes, int n_in,
                              void* d_out, int out_size)
{
    const float* Q0 = (const float*)d_in[0];  // logQ0 [B,K,K]
    const float* Q1 = (const float*)d_in[1];  // logQ1 [B,K,K]
    const float* P0 = (const float*)d_in[2];  // logP0 [B,1,K]
    const float* P1 = (const float*)d_in[3];  // logP1 [B,K,K]
    const float* P2 = (const float*)d_in[4];  // logP2 [B,K,1]

    dim3 g1(NSL, BATCH);
    k_colsum_q1<<<g1, 256>>>(Q1);

    dim3 g2(2 * NSL, BATCH);
    k_mid_q0<<<g2, TPB>>>(P0, P1, Q0);

    dim3 g3(JSPL, BATCH);
    k_final<<<g3, TPB>>>(P2, (float*)d_out);
}

// round 17
// speedup vs baseline: 1.0520x; 1.0091x over previous
#include <cuda_runtime.h>
#include <math.h>

#define BATCH  128
#define KK     512
#define NSL    8      // i-slices of 64 rows
#define SLR    64
#define TPB    128    // thread owns 4 columns (float4)
#define JSPL   4      // j-chunks in k_final

#define LOGK 6.2383246250395077632f   // log(512)

// Scratch (__device__ globals). Fits in L2; streaming input loads use __ldcs
// (evict-first) so these stay resident.
__device__ float g_Ep0[NSL * BATCH * KK];   // partial col-sums of exp(Q0) (2 MB)
__device__ float g_Ep1[NSL * BATCH * KK];   // partial col-sums of exp(Q1) (2 MB)
__device__ float g_mmp[NSL * BATCH * KK];   // partial mm sums (2 MB)
__device__ float g_sp[BATCH * JSPL];        // per-(b,chunk) t partial sums
__device__ unsigned int g_tickF;            // zero-init; last block resets

__device__ __forceinline__ float4 ldcs4(const float4* p) { return __ldcs(p); }

// ---------------------------------------------------------------------------
// Kernel 1: partial column sums of exp(Q1). grid = 1024 blocks x 128.
// Fires the PDL trigger immediately so K2's sync-free Q0 blocks can tail-fill
// this kernel's drain. Memory safety for consumers comes from K2's
// cudaGridDependencySynchronize(), not from trigger placement.
// ---------------------------------------------------------------------------
__global__ void __launch_bounds__(TPB, 14) k_colsum_q1(const float* __restrict__ Q1)
{
    cudaTriggerProgrammaticLaunchCompletion();

    const int slice = blockIdx.x & 7;
    const int b     = blockIdx.x >> 3;
    const int t     = threadIdx.x;

    const float4* p = (const float4*)(Q1 + (size_t)b * KK * KK
                                         + (size_t)(slice * SLR) * KK) + t;
    const int rs = KK / 4;

    float sx = 0.f, sy = 0.f, sz = 0.f, sw = 0.f;
#pragma unroll
    for (int i = 0; i < SLR; i += 4) {
        float4 a0 = ldcs4(p + (i + 0) * rs);
        float4 a1 = ldcs4(p + (i + 1) * rs);
        float4 a2 = ldcs4(p + (i + 2) * rs);
        float4 a3 = ldcs4(p + (i + 3) * rs);
        sx += __expf(a0.x) + __expf(a1.x) + __expf(a2.x) + __expf(a3.x);
        sy += __expf(a0.y) + __expf(a1.y) + __expf(a2.y) + __expf(a3.y);
        sz += __expf(a0.z) + __expf(a1.z) + __expf(a2.z) + __expf(a3.z);
        sw += __expf(a0.w) + __expf(a1.w) + __expf(a2.w) + __expf(a3.w);
    }
    ((float4*)(g_Ep1 + ((size_t)slice * BATCH + b) * KK))[t] =
        make_float4(sx, sy, sz, sw);
}

// ---------------------------------------------------------------------------
// Kernel 2 (PDL secondary, 1D grid of 2048 blocks):
//   bid [0,1024)    : Q0 colsum — independent of K1, NO sync: these launch
//                     first and tail-fill K1's drain.
//   bid [1024,2048) : mid path — cudaGridDependencySynchronize() (waits for
//                     K1 completion + memory flush), then ew prologue and the
//                     proven P1 streaming body.
// Fires its own trigger early so K3 can overlap this kernel's drain.
// ---------------------------------------------------------------------------
__global__ void __launch_bounds__(TPB, 14) k_mid_q0(const float* __restrict__ P0,
                                                    const float* __restrict__ P1,
                                                    const float* __restrict__ Q0)
{
    cudaTriggerProgrammaticLaunchCompletion();

    const int bid = blockIdx.x;
    const int t   = threadIdx.x;
    const int rs  = KK / 4;

    if (bid < NSL * BATCH) {
        // ----- Q0 colsum path (sync-free) -----
        const int slice = bid & 7;
        const int b     = bid >> 3;

        const float4* p = (const float4*)(Q0 + (size_t)b * KK * KK
                                             + (size_t)(slice * SLR) * KK) + t;

        float sx = 0.f, sy = 0.f, sz = 0.f, sw = 0.f;
#pragma unroll
        for (int i = 0; i < SLR; i += 4) {
            float4 a0 = ldcs4(p + (i + 0) * rs);
            float4 a1 = ldcs4(p + (i + 1) * rs);
            float4 a2 = ldcs4(p + (i + 2) * rs);
            float4 a3 = ldcs4(p + (i + 3) * rs);
            sx += __expf(a0.x) + __expf(a1.x) + __expf(a2.x) + __expf(a3.x);
            sy += __expf(a0.y) + __expf(a1.y) + __expf(a2.y) + __expf(a3.y);
            sz += __expf(a0.z) + __expf(a1.z) + __expf(a2.z) + __expf(a3.z);
            sw += __expf(a0.w) + __expf(a1.w) + __expf(a2.w) + __expf(a3.w);
        }
        ((float4*)(g_Ep0 + ((size_t)slice * BATCH + b) * KK))[t] =
            make_float4(sx, sy, sz, sw);
    } else {
        // ----- mid path (needs K1's g_Ep1) -----
        const int idx   = bid - NSL * BATCH;
        const int slice = idx & 7;
        const int b     = idx >> 3;
        const int i0    = slice * SLR;

        cudaGridDependencySynchronize();   // K1 complete + stores visible

        __shared__ float ew[SLR];
        if (t < SLR) {
            const int i = i0 + t;
            float e1 = g_Ep1[((size_t)0 * BATCH + b) * KK + i];
#pragma unroll
            for (int s = 1; s < NSL; s++)
                e1 += g_Ep1[((size_t)s * BATCH + b) * KK + i];
            ew[t] = __expf(P0[b * KK + i]) * (float)KK / e1;
        }
        __syncthreads();

        const float4* p = (const float4*)(P1 + (size_t)b * KK * KK
                                             + (size_t)i0 * KK) + t;

        float sx = 0.f, sy = 0.f, sz = 0.f, sw = 0.f;
#pragma unroll
        for (int i = 0; i < SLR; i += 4) {
            float4 a0 = ldcs4(p + (i + 0) * rs);
            float4 a1 = ldcs4(p + (i + 1) * rs);
            float4 a2 = ldcs4(p + (i + 2) * rs);
            float4 a3 = ldcs4(p + (i + 3) * rs);
            float w0 = ew[i + 0], w1 = ew[i + 1], w2 = ew[i + 2], w3 = ew[i + 3];
            sx += w0 * __expf(a0.x) + w1 * __expf(a1.x)
                + w2 * __expf(a2.x) + w3 * __expf(a3.x);
            sy += w0 * __expf(a0.y) + w1 * __expf(a1.y)
                + w2 * __expf(a2.y) + w3 * __expf(a3.y);
            sz += w0 * __expf(a0.z) + w1 * __expf(a1.z)
                + w2 * __expf(a2.z) + w3 * __expf(a3.z);
            sw += w0 * __expf(a0.w) + w1 * __expf(a1.w)
                + w2 * __expf(a2.w) + w3 * __expf(a3.w);
        }
        ((float4*)(g_mmp + ((size_t)slice * BATCH + b) * KK))[t] =
            make_float4(sx, sy, sz, sw);
    }
}

// ---------------------------------------------------------------------------
// Kernel 3 (PDL secondary): t partials + deterministic finish.
// grid = (JSPL, BATCH) = 512 blocks, block = 128. Syncs on K2's completion,
// so its launch ramp overlaps K2's drain.
// ---------------------------------------------------------------------------
__global__ void __launch_bounds__(TPB) k_final(const float* __restrict__ P2,
                                               float* __restrict__ out)
{
    cudaGridDependencySynchronize();       // K2 complete + stores visible

    const int js = blockIdx.x;
    const int b  = blockIdx.y;
    const int t  = threadIdx.x;
    const int j  = js * TPB + t;

    float m = 0.f, e0 = 0.f;
#pragma unroll
    for (int s = 0; s < NSL; s++) {
        m  += g_mmp[((size_t)s * BATCH + b) * KK + j];
        e0 += g_Ep0[((size_t)s * BATCH + b) * KK + j];
    }
    float acc = m / e0 * __expf(P2[b * KK + j]);

#pragma unroll
    for (int o = 16; o; o >>= 1)
        acc += __shfl_down_sync(0xFFFFFFFFu, acc, o);

    __shared__ float red[4];
    if ((t & 31) == 0) red[t >> 5] = acc;
    __syncthreads();

    __shared__ bool amLast;
    if (t == 0) {
        g_sp[b * JSPL + js] = (red[0] + red[1]) + (red[2] + red[3]);
        __threadfence();
        amLast = (atomicAdd(&g_tickF, 1u) == BATCH * JSPL - 1);
    }
    __syncthreads();

    if (amLast) {
        __shared__ float sm[BATCH];
        float s = (g_sp[t * JSPL + 0] + g_sp[t * JSPL + 1])
                + (g_sp[t * JSPL + 2] + g_sp[t * JSPL + 3]);
        sm[t] = LOGK - logf(s);
        __syncthreads();
#pragma unroll
        for (int off = BATCH / 2; off > 0; off >>= 1) {
            if (t < off) sm[t] += sm[t + off];
            __syncthreads();
        }
        if (t == 0) {
            out[0] = sm[0];
            g_tickF = 0;   // reset for graph replay
        }
    }
}

// ---------------------------------------------------------------------------
extern "C" void kernel_launch(void* const* d_in, const int* in_sizes, int n_in,
                              void* d_out, int out_size)
{
    const float* Q0 = (const float*)d_in[0];  // logQ0 [B,K,K]
    const float* Q1 = (const float*)d_in[1];  // logQ1 [B,K,K]
    const float* P0 = (const float*)d_in[2];  // logP0 [B,1,K]
    const float* P1 = (const float*)d_in[3];  // logP1 [B,K,K]
    const float* P2 = (const float*)d_in[4];  // logP2 [B,K,1]

    // K1: primary (plain launch)
    k_colsum_q1<<<NSL * BATCH, TPB>>>(Q1);

    // K2: PDL secondary — may begin launching while K1 drains
    {
        cudaLaunchConfig_t cfg = {};
        cfg.gridDim  = dim3(2 * NSL * BATCH, 1, 1);
        cfg.blockDim = dim3(TPB, 1, 1);
        cudaLaunchAttribute attr[1];
        attr[0].id = cudaLaunchAttributeProgrammaticStreamSerialization;
        attr[0].val.programmaticStreamSerializationAllowed = 1;
        cfg.attrs = attr;
        cfg.numAttrs = 1;
        cudaLaunchKernelEx(&cfg, k_mid_q0, P0, P1, Q0);
    }

    // K3: PDL secondary — ramp overlaps K2's drain
    {
        cudaLaunchConfig_t cfg = {};
        cfg.gridDim  = dim3(JSPL, BATCH, 1);
        cfg.blockDim = dim3(TPB, 1, 1);
        cudaLaunchAttribute attr[1];
        attr[0].id = cudaLaunchAttributeProgrammaticStreamSerialization;
        attr[0].val.programmaticStreamSerializationAllowed = 1;
        cfg.attrs = attr;
        cfg.numAttrs = 1;
        cudaLaunchKernelEx(&cfg, k_final, P2, (float*)d_out);
    }
}